// round 3
// baseline (speedup 1.0000x reference)
#include <cuda_runtime.h>
#include <cuda_fp16.h>

#define NMAX 50000
#define EMAX 800000
#define TOTE (NMAX + EMAX)

// ---- scratch (device globals: no allocation allowed) ----
__device__ int g_cnt[NMAX];          // packed: low16 = degree (incl self), high16 = count(type0) incl self
__device__ int g_rowptr[NMAX + 1];
__device__ int g_cur[NMAX];
__device__ int g_adj[TOTE];
__device__ __align__(16) float g_hl0[256];   // layer-0 linear output, 2 rows x 128
__device__ float g_ew[4];                    // exp(beta0[r,h] - max_r beta0[r,h]) : [r*2+h]
__device__ __align__(16) float g_hlinf[(size_t)NMAX * 128];  // layer-1 linear output fp32 (self reads)
__device__ __align__(16) __half g_hlinh[(size_t)NMAX * 128]; // fp16 copy (neighbor gathers)
__device__ __align__(16) float g_beta[(size_t)NMAX * 2];     // layer-1 logits per node/head

__device__ __forceinline__ float leaky(float v) { return v > 0.f ? v : 0.2f * v; }

// exp(x) for x <= 0, FMA-pipe only (no MUFU). Taylor-6 on 2^f, f in [0,1).
__device__ __forceinline__ float fexp(float x) {
    float t = fmaxf(x * 1.4426950408889634f, -126.f);
    float n = floorf(t);
    float f = t - n;
    float p = 1.5403530394e-4f;
    p = fmaf(p, f, 1.3333558146e-3f);
    p = fmaf(p, f, 9.6181291076e-3f);
    p = fmaf(p, f, 5.5504108665e-2f);
    p = fmaf(p, f, 2.4022650696e-1f);
    p = fmaf(p, f, 6.9314718056e-1f);
    p = fmaf(p, f, 1.0f);
    float s = __int_as_float(((int)n + 127) << 23);
    return p * s;
}

// ======================= CSR build =======================
__global__ void k_init(const int* __restrict__ x, int n) {
    int i = blockIdx.x * blockDim.x + threadIdx.x;
    if (i < n) g_cnt[i] = 1 + ((x[i] == 0) << 16);   // self-loop
}

__global__ void k_hist(const int* __restrict__ ei, const int* __restrict__ x, int E) {
    int e = blockIdx.x * blockDim.x + threadIdx.x;
    if (e < E) {
        int d = ei[E + e];
        int p = 1 + ((__ldg(&x[d]) == 0) << 16);
        atomicAdd(&g_cnt[ei[e]], p);
    }
}

// single block: prefix sum of degrees + scatter-init + layer-0 prep (tiny)
__global__ void k_scan(int n, const float* __restrict__ emb, const float* __restrict__ Ws,
                       const float* __restrict__ bs, const float* __restrict__ atts) {
    __shared__ int part[1024];
    __shared__ float sh[256];
    __shared__ float sb4[4];
    int t = threadIdx.x;
    int chunk = (n + 1023) >> 10;
    int beg = t * chunk;
    int end = min(beg + chunk, n);
    int s = 0;
    for (int i = beg; i < end; i++) s += (g_cnt[i] & 0xffff);
    part[t] = s;
    __syncthreads();
    for (int off = 1; off < 1024; off <<= 1) {
        int tmp = (t >= off) ? part[t - off] : 0;
        __syncthreads();
        part[t] += tmp;
        __syncthreads();
    }
    int run = part[t] - s;
    for (int i = beg; i < end; i++) {
        int deg = g_cnt[i] & 0xffff;
        g_rowptr[i] = run;
        g_adj[run] = i;       // self-loop first
        g_cur[i] = run + 1;
        run += deg;
    }
    if (t == 0) g_rowptr[n] = part[1023];
    __syncthreads();
    // layer-0 linear (2 rows x 128)
    if (t < 256) {
        int row = t >> 7, col = t & 127;
        float acc = bs[col];
#pragma unroll
        for (int k = 0; k < 64; k++) acc += emb[row * 64 + k] * Ws[k * 128 + col];
        g_hl0[t] = acc;
        sh[t] = acc;
    }
    __syncthreads();
    if (t < 4) {
        int r = t >> 1, h = t & 1;
        float sum = 0.f;
        for (int d = 0; d < 64; d++) sum += sh[r * 128 + h * 64 + d] * atts[h * 64 + d];
        sb4[r * 2 + h] = leaky(sum);
    }
    __syncthreads();
    if (t < 4) {
        int h = t & 1;
        float m = fmaxf(sb4[h], sb4[2 + h]);
        g_ew[t] = fexp(sb4[t] - m);
    }
}

__global__ void k_scatter(const int* __restrict__ ei, int E) {
    int e = blockIdx.x * blockDim.x + threadIdx.x;
    if (e < E) {
        int s = ei[e];
        int d = ei[E + e];
        int p = atomicAdd(&g_cur[s], 1);
        g_adj[p] = d;
    }
}

// ======================= fused node kernel =======================
// Layer-0 aggregation (closed form from type counts) -> layer-1 linear (warp-per-node)
// -> layer-1 attention logits. No adjacency reads, no exp.
__global__ __launch_bounds__(256) void k_node(const int* __restrict__ x,
                                              const float* __restrict__ Ws,
                                              const float* __restrict__ bs,
                                              const float* __restrict__ atts,
                                              const float* __restrict__ biases, int n_nodes) {
    __shared__ float4 sW[64 * 32];  // sW[k*32+l] = {W1[k][l], W1[k][l+32], W1[k][l+64], W1[k][l+96]}
    __shared__ float sx[8][64];
    __shared__ float sh0[256];
    __shared__ float sew[4];
    const float* W1 = Ws + 64 * 128;
    const float* b1 = bs + 128;
    const float* att1 = atts + 128;
    for (int idx = threadIdx.x; idx < 2048; idx += 256) {
        int k = idx >> 5, l = idx & 31;
        const float* wr = W1 + k * 128 + l;
        sW[idx] = make_float4(wr[0], wr[32], wr[64], wr[96]);
    }
    for (int idx = threadIdx.x; idx < 256; idx += 256) sh0[idx] = g_hl0[idx];
    if (threadIdx.x < 4) sew[threadIdx.x] = g_ew[threadIdx.x];
    __syncthreads();

    int warp = threadIdx.x >> 5, lane = threadIdx.x & 31;
    int n = blockIdx.x * 8 + warp;
    if (n >= n_nodes) return;

    int packed = g_cnt[n];
    float deg = (float)(packed & 0xffff);
    float c0f = (float)(packed >> 16);
    float c1f = deg - c0f;
    // per-head softmax-weighted neighbor mix coefficients
    float w00 = sew[0], w01 = sew[1], w10 = sew[2], w11 = sew[3];
    float den0 = c0f * w00 + c1f * w10 + 1e-16f;
    float den1 = c0f * w01 + c1f * w11 + 1e-16f;
    float A0 = c0f * w00 / den0, B0 = c1f * w10 / den0;
    float A1 = c0f * w01 / den1, B1 = c1f * w11 / den1;
    int tp = x[n];
    const float* vt = sh0 + (tp ? 128 : 0);

    // layer-0 output for d = lane, lane+32 (mean over heads + bias, relu)
#pragma unroll
    for (int r = 0; r < 2; r++) {
        int d = lane + r * 32;
        float f0 = deg * vt[d] + A0 * sh0[d] + B0 * sh0[128 + d];           // head 0 (col d)
        float f1 = deg * vt[64 + d] + A1 * sh0[64 + d] + B1 * sh0[192 + d]; // head 1 (col 64+d)
        sx[warp][d] = fmaxf(0.f, fmaf(0.5f, f0 + f1, biases[d]));
    }
    __syncwarp();

    // layer-1 linear: [64] @ W1[64,128] + b1
    float4 acc = make_float4(b1[lane], b1[lane + 32], b1[lane + 64], b1[lane + 96]);
#pragma unroll
    for (int k = 0; k < 64; k++) {
        float xk = sx[warp][k];
        float4 w = sW[(k << 5) + lane];
        acc.x = fmaf(xk, w.x, acc.x);
        acc.y = fmaf(xk, w.y, acc.y);
        acc.z = fmaf(xk, w.z, acc.z);
        acc.w = fmaf(xk, w.w, acc.w);
    }
    float* o = g_hlinf + (size_t)n * 128;
    o[lane] = acc.x;
    o[lane + 32] = acc.y;
    o[lane + 64] = acc.z;
    o[lane + 96] = acc.w;
    __half* oh = g_hlinh + (size_t)n * 128;
    oh[lane] = __float2half_rn(acc.x);
    oh[lane + 32] = __float2half_rn(acc.y);
    oh[lane + 64] = __float2half_rn(acc.z);
    oh[lane + 96] = __float2half_rn(acc.w);
    // attention logits: head0 = cols [0,64), head1 = cols [64,128)
    float p0 = acc.x * att1[lane] + acc.y * att1[lane + 32];
    float p1 = acc.z * att1[64 + lane] + acc.w * att1[96 + lane];
#pragma unroll
    for (int off = 16; off; off >>= 1) {
        p0 += __shfl_xor_sync(0xffffffffu, p0, off);
        p1 += __shfl_xor_sync(0xffffffffu, p1, off);
    }
    if (lane == 0) {
        g_beta[2 * n] = leaky(p0);
        g_beta[2 * n + 1] = leaky(p1);
    }
}

// ======================= layer-1 aggregation =======================
// Warp per node. Pass 1: segment max (no exp). Pass 2: chunks of 32 edges —
// each lane computes the softmax weight for ITS edge once (FMA-pipe exp), parks
// it in smem; the vector-gather loop broadcasts weights via LDS. fp16 gathers.
__global__ __launch_bounds__(256) void k_aggr(const float* __restrict__ biases,
                                              float* __restrict__ out, int n_nodes) {
    __shared__ int sd[8][32];
    __shared__ float2 swt[8][32];
    int warp = threadIdx.x >> 5, lane = threadIdx.x & 31;
    int n = blockIdx.x * 8 + warp;
    if (n >= n_nodes) return;
    int s = g_rowptr[n], e = g_rowptr[n + 1];

    // pass 1: per-head max over neighbors
    float m0 = -3e38f, m1 = -3e38f;
    for (int i = s + lane; i < e; i += 32) {
        int d = g_adj[i];
        float2 b = *(const float2*)(g_beta + 2 * d);
        m0 = fmaxf(m0, b.x);
        m1 = fmaxf(m1, b.y);
    }
#pragma unroll
    for (int o = 16; o; o >>= 1) {
        m0 = fmaxf(m0, __shfl_xor_sync(0xffffffffu, m0, o));
        m1 = fmaxf(m1, __shfl_xor_sync(0xffffffffu, m1, o));
    }

    int head = lane >> 4;  // lane covers columns [4*lane, 4*lane+4)
    float4 acc = make_float4(0.f, 0.f, 0.f, 0.f);
    float den0 = 0.f, den1 = 0.f;

    for (int base = s; base < e; base += 32) {
        int i = base + lane;
        bool valid = i < e;
        int d = valid ? g_adj[i] : 0;
        float w0 = 0.f, w1 = 0.f;
        if (valid) {
            float2 b = *(const float2*)(g_beta + 2 * d);
            w0 = fexp(b.x - m0);
            w1 = fexp(b.y - m1);
        }
        sd[warp][lane] = d;
        swt[warp][lane] = make_float2(w0, w1);
        den0 += w0;
        den1 += w1;
        __syncwarp();
        int cnt = min(32, e - base);
#pragma unroll 4
        for (int j = 0; j < cnt; j++) {
            int dd = sd[warp][j];
            float2 wp = swt[warp][j];
            float w = head ? wp.y : wp.x;
            const uint2* rowh = (const uint2*)(g_hlinh + (size_t)dd * 128);
            uint2 pk = __ldg(&rowh[lane]);
            __half2 h01 = *(__half2*)&pk.x;
            __half2 h23 = *(__half2*)&pk.y;
            float2 f01 = __half22float2(h01);
            float2 f23 = __half22float2(h23);
            acc.x = fmaf(w, f01.x, acc.x);
            acc.y = fmaf(w, f01.y, acc.y);
            acc.z = fmaf(w, f23.x, acc.z);
            acc.w = fmaf(w, f23.y, acc.w);
        }
        __syncwarp();
    }
#pragma unroll
    for (int o = 16; o; o >>= 1) {
        den0 += __shfl_xor_sync(0xffffffffu, den0, o);
        den1 += __shfl_xor_sync(0xffffffffu, den1, o);
    }
    float inv = 1.f / ((head ? den1 : den0) + 1e-16f);
    float deg = (float)(e - s);
    float4 hv = *(const float4*)(g_hlinf + (size_t)n * 128 + (lane << 2));
    float4 r;
    r.x = fmaf(deg, hv.x, acc.x * inv);
    r.y = fmaf(deg, hv.y, acc.y * inv);
    r.z = fmaf(deg, hv.z, acc.z * inv);
    r.w = fmaf(deg, hv.w, acc.w * inv);
    float4 q;
    q.x = __shfl_xor_sync(0xffffffffu, r.x, 16);
    q.y = __shfl_xor_sync(0xffffffffu, r.y, 16);
    q.z = __shfl_xor_sync(0xffffffffu, r.z, 16);
    q.w = __shfl_xor_sync(0xffffffffu, r.w, 16);
    if (lane < 16) {
        int dl = lane << 2;
        float4 o4;
        o4.x = 0.5f * (r.x + q.x) + biases[64 + dl + 0];
        o4.y = 0.5f * (r.y + q.y) + biases[64 + dl + 1];
        o4.z = 0.5f * (r.z + q.z) + biases[64 + dl + 2];
        o4.w = 0.5f * (r.w + q.w) + biases[64 + dl + 3];
        *(float4*)(out + (size_t)n * 64 + dl) = o4;
    }
}

// ======================= launch =======================
extern "C" void kernel_launch(void* const* d_in, const int* in_sizes, int n_in,
                              void* d_out, int out_size) {
    const int* x = (const int*)d_in[0];
    const int* ei = (const int*)d_in[1];
    const float* emb = (const float*)d_in[2];
    const float* Ws = (const float*)d_in[3];
    const float* bs = (const float*)d_in[4];
    const float* atts = (const float*)d_in[5];
    const float* biases = (const float*)d_in[6];
    float* out = (float*)d_out;

    int n = in_sizes[0];
    int E = in_sizes[1] / 2;

    int nb = (n + 255) / 256;
    int eb = (E + 255) / 256;
    int wb = (n + 7) / 8;

    k_init<<<nb, 256>>>(x, n);
    k_hist<<<eb, 256>>>(ei, x, E);
    k_scan<<<1, 1024>>>(n, emb, Ws, bs, atts);
    k_scatter<<<eb, 256>>>(ei, E);
    k_node<<<wb, 256>>>(x, Ws, bs, atts, biases, n);
    k_aggr<<<wb, 256>>>(biases, out, n);
}

// round 4
// speedup vs baseline: 1.0001x; 1.0001x over previous
#include <cuda_runtime.h>
#include <cuda_fp16.h>

#define NMAX 50000
#define EMAX 800000
#define TOTE (NMAX + EMAX)

// ---- scratch (device globals: no allocation allowed) ----
__device__ int g_cnt[NMAX];          // packed: low16 = degree (incl self), high16 = count(type0) incl self
__device__ int g_rowptr[NMAX + 1];
__device__ int g_cur[NMAX];
__device__ int g_adj[TOTE];
__device__ __align__(16) float g_hl0[256];   // layer-0 linear output, 2 rows x 128
__device__ float g_ew[4];                    // exp(beta0[r,h] - max_r beta0[r,h]) : [r*2+h]
__device__ __align__(16) float g_hlinf[(size_t)NMAX * 128];  // layer-1 linear output fp32 (self reads)
__device__ __align__(16) __half g_hlinh[(size_t)NMAX * 128]; // fp16 copy (neighbor gathers)
__device__ __align__(16) float g_beta[(size_t)NMAX * 2];     // layer-1 logits per node/head

__device__ __forceinline__ float leaky(float v) { return v > 0.f ? v : 0.2f * v; }

// exp(x) for x <= 0, FMA-pipe only (no MUFU). Taylor-6 on 2^f, f in [0,1).
__device__ __forceinline__ float fexp(float x) {
    float t = fmaxf(x * 1.4426950408889634f, -126.f);
    float n = floorf(t);
    float f = t - n;
    float p = 1.5403530394e-4f;
    p = fmaf(p, f, 1.3333558146e-3f);
    p = fmaf(p, f, 9.6181291076e-3f);
    p = fmaf(p, f, 5.5504108665e-2f);
    p = fmaf(p, f, 2.4022650696e-1f);
    p = fmaf(p, f, 6.9314718056e-1f);
    p = fmaf(p, f, 1.0f);
    float s = __int_as_float(((int)n + 127) << 23);
    return p * s;
}

// ======================= CSR build =======================
__global__ void k_init(const int* __restrict__ x, int n) {
    int i = blockIdx.x * blockDim.x + threadIdx.x;
    if (i < n) g_cnt[i] = 1 + ((x[i] == 0) << 16);   // self-loop
}

__global__ void k_hist(const int* __restrict__ ei, const int* __restrict__ x, int E) {
    int e = blockIdx.x * blockDim.x + threadIdx.x;
    if (e < E) {
        int d = ei[E + e];
        int p = 1 + ((__ldg(&x[d]) == 0) << 16);
        atomicAdd(&g_cnt[ei[e]], p);
    }
}

// single block: prefix sum of degrees + scatter-init + layer-0 prep (tiny)
__global__ void k_scan(int n, const float* __restrict__ emb, const float* __restrict__ Ws,
                       const float* __restrict__ bs, const float* __restrict__ atts) {
    __shared__ int part[1024];
    __shared__ float sh[256];
    __shared__ float sb4[4];
    int t = threadIdx.x;
    int chunk = (n + 1023) >> 10;
    int beg = t * chunk;
    int end = min(beg + chunk, n);
    int s = 0;
    for (int i = beg; i < end; i++) s += (g_cnt[i] & 0xffff);
    part[t] = s;
    __syncthreads();
    for (int off = 1; off < 1024; off <<= 1) {
        int tmp = (t >= off) ? part[t - off] : 0;
        __syncthreads();
        part[t] += tmp;
        __syncthreads();
    }
    int run = part[t] - s;
    for (int i = beg; i < end; i++) {
        int deg = g_cnt[i] & 0xffff;
        g_rowptr[i] = run;
        g_adj[run] = i;       // self-loop first
        g_cur[i] = run + 1;
        run += deg;
    }
    if (t == 0) g_rowptr[n] = part[1023];
    __syncthreads();
    // layer-0 linear (2 rows x 128)
    if (t < 256) {
        int row = t >> 7, col = t & 127;
        float acc = bs[col];
#pragma unroll
        for (int k = 0; k < 64; k++) acc += emb[row * 64 + k] * Ws[k * 128 + col];
        g_hl0[t] = acc;
        sh[t] = acc;
    }
    __syncthreads();
    if (t < 4) {
        int r = t >> 1, h = t & 1;
        float sum = 0.f;
        for (int d = 0; d < 64; d++) sum += sh[r * 128 + h * 64 + d] * atts[h * 64 + d];
        sb4[r * 2 + h] = leaky(sum);
    }
    __syncthreads();
    if (t < 4) {
        int h = t & 1;
        float m = fmaxf(sb4[h], sb4[2 + h]);
        g_ew[t] = fexp(sb4[t] - m);
    }
}

__global__ void k_scatter(const int* __restrict__ ei, int E) {
    int e = blockIdx.x * blockDim.x + threadIdx.x;
    if (e < E) {
        int s = ei[e];
        int d = ei[E + e];
        int p = atomicAdd(&g_cur[s], 1);
        g_adj[p] = d;
    }
}

// ======================= fused node kernel =======================
// Layer-0 aggregation (closed form from type counts) -> layer-1 linear (warp-per-node)
// -> layer-1 attention logits. No adjacency reads, no exp.
__global__ __launch_bounds__(256) void k_node(const int* __restrict__ x,
                                              const float* __restrict__ Ws,
                                              const float* __restrict__ bs,
                                              const float* __restrict__ atts,
                                              const float* __restrict__ biases, int n_nodes) {
    __shared__ float4 sW[64 * 32];  // sW[k*32+l] = {W1[k][l], W1[k][l+32], W1[k][l+64], W1[k][l+96]}
    __shared__ float sx[8][64];
    __shared__ float sh0[256];
    __shared__ float sew[4];
    const float* W1 = Ws + 64 * 128;
    const float* b1 = bs + 128;
    const float* att1 = atts + 128;
    for (int idx = threadIdx.x; idx < 2048; idx += 256) {
        int k = idx >> 5, l = idx & 31;
        const float* wr = W1 + k * 128 + l;
        sW[idx] = make_float4(wr[0], wr[32], wr[64], wr[96]);
    }
    for (int idx = threadIdx.x; idx < 256; idx += 256) sh0[idx] = g_hl0[idx];
    if (threadIdx.x < 4) sew[threadIdx.x] = g_ew[threadIdx.x];
    __syncthreads();

    int warp = threadIdx.x >> 5, lane = threadIdx.x & 31;
    int n = blockIdx.x * 8 + warp;
    if (n >= n_nodes) return;

    int packed = g_cnt[n];
    float deg = (float)(packed & 0xffff);
    float c0f = (float)(packed >> 16);
    float c1f = deg - c0f;
    // per-head softmax-weighted neighbor mix coefficients
    float w00 = sew[0], w01 = sew[1], w10 = sew[2], w11 = sew[3];
    float den0 = c0f * w00 + c1f * w10 + 1e-16f;
    float den1 = c0f * w01 + c1f * w11 + 1e-16f;
    float A0 = c0f * w00 / den0, B0 = c1f * w10 / den0;
    float A1 = c0f * w01 / den1, B1 = c1f * w11 / den1;
    int tp = x[n];
    const float* vt = sh0 + (tp ? 128 : 0);

    // layer-0 output for d = lane, lane+32 (mean over heads + bias, relu)
#pragma unroll
    for (int r = 0; r < 2; r++) {
        int d = lane + r * 32;
        float f0 = deg * vt[d] + A0 * sh0[d] + B0 * sh0[128 + d];           // head 0 (col d)
        float f1 = deg * vt[64 + d] + A1 * sh0[64 + d] + B1 * sh0[192 + d]; // head 1 (col 64+d)
        sx[warp][d] = fmaxf(0.f, fmaf(0.5f, f0 + f1, biases[d]));
    }
    __syncwarp();

    // layer-1 linear: [64] @ W1[64,128] + b1
    float4 acc = make_float4(b1[lane], b1[lane + 32], b1[lane + 64], b1[lane + 96]);
#pragma unroll
    for (int k = 0; k < 64; k++) {
        float xk = sx[warp][k];
        float4 w = sW[(k << 5) + lane];
        acc.x = fmaf(xk, w.x, acc.x);
        acc.y = fmaf(xk, w.y, acc.y);
        acc.z = fmaf(xk, w.z, acc.z);
        acc.w = fmaf(xk, w.w, acc.w);
    }
    float* o = g_hlinf + (size_t)n * 128;
    o[lane] = acc.x;
    o[lane + 32] = acc.y;
    o[lane + 64] = acc.z;
    o[lane + 96] = acc.w;
    __half* oh = g_hlinh + (size_t)n * 128;
    oh[lane] = __float2half_rn(acc.x);
    oh[lane + 32] = __float2half_rn(acc.y);
    oh[lane + 64] = __float2half_rn(acc.z);
    oh[lane + 96] = __float2half_rn(acc.w);
    // attention logits: head0 = cols [0,64), head1 = cols [64,128)
    float p0 = acc.x * att1[lane] + acc.y * att1[lane + 32];
    float p1 = acc.z * att1[64 + lane] + acc.w * att1[96 + lane];
#pragma unroll
    for (int off = 16; off; off >>= 1) {
        p0 += __shfl_xor_sync(0xffffffffu, p0, off);
        p1 += __shfl_xor_sync(0xffffffffu, p1, off);
    }
    if (lane == 0) {
        g_beta[2 * n] = leaky(p0);
        g_beta[2 * n + 1] = leaky(p1);
    }
}

// ======================= layer-1 aggregation =======================
// Warp per node. Pass 1: segment max (no exp). Pass 2: chunks of 32 edges —
// each lane computes the softmax weight for ITS edge once (FMA-pipe exp), parks
// it in smem; the vector-gather loop broadcasts weights via LDS. fp16 gathers.
__global__ __launch_bounds__(256) void k_aggr(const float* __restrict__ biases,
                                              float* __restrict__ out, int n_nodes) {
    __shared__ int sd[8][32];
    __shared__ float2 swt[8][32];
    int warp = threadIdx.x >> 5, lane = threadIdx.x & 31;
    int n = blockIdx.x * 8 + warp;
    if (n >= n_nodes) return;
    int s = g_rowptr[n], e = g_rowptr[n + 1];

    // pass 1: per-head max over neighbors
    float m0 = -3e38f, m1 = -3e38f;
    for (int i = s + lane; i < e; i += 32) {
        int d = g_adj[i];
        float2 b = *(const float2*)(g_beta + 2 * d);
        m0 = fmaxf(m0, b.x);
        m1 = fmaxf(m1, b.y);
    }
#pragma unroll
    for (int o = 16; o; o >>= 1) {
        m0 = fmaxf(m0, __shfl_xor_sync(0xffffffffu, m0, o));
        m1 = fmaxf(m1, __shfl_xor_sync(0xffffffffu, m1, o));
    }

    int head = lane >> 4;  // lane covers columns [4*lane, 4*lane+4)
    float4 acc = make_float4(0.f, 0.f, 0.f, 0.f);
    float den0 = 0.f, den1 = 0.f;

    for (int base = s; base < e; base += 32) {
        int i = base + lane;
        bool valid = i < e;
        int d = valid ? g_adj[i] : 0;
        float w0 = 0.f, w1 = 0.f;
        if (valid) {
            float2 b = *(const float2*)(g_beta + 2 * d);
            w0 = fexp(b.x - m0);
            w1 = fexp(b.y - m1);
        }
        sd[warp][lane] = d;
        swt[warp][lane] = make_float2(w0, w1);
        den0 += w0;
        den1 += w1;
        __syncwarp();
        int cnt = min(32, e - base);
#pragma unroll 4
        for (int j = 0; j < cnt; j++) {
            int dd = sd[warp][j];
            float2 wp = swt[warp][j];
            float w = head ? wp.y : wp.x;
            const uint2* rowh = (const uint2*)(g_hlinh + (size_t)dd * 128);
            uint2 pk = __ldg(&rowh[lane]);
            __half2 h01 = *(__half2*)&pk.x;
            __half2 h23 = *(__half2*)&pk.y;
            float2 f01 = __half22float2(h01);
            float2 f23 = __half22float2(h23);
            acc.x = fmaf(w, f01.x, acc.x);
            acc.y = fmaf(w, f01.y, acc.y);
            acc.z = fmaf(w, f23.x, acc.z);
            acc.w = fmaf(w, f23.y, acc.w);
        }
        __syncwarp();
    }
#pragma unroll
    for (int o = 16; o; o >>= 1) {
        den0 += __shfl_xor_sync(0xffffffffu, den0, o);
        den1 += __shfl_xor_sync(0xffffffffu, den1, o);
    }
    float inv = 1.f / ((head ? den1 : den0) + 1e-16f);
    float deg = (float)(e - s);
    float4 hv = *(const float4*)(g_hlinf + (size_t)n * 128 + (lane << 2));
    float4 r;
    r.x = fmaf(deg, hv.x, acc.x * inv);
    r.y = fmaf(deg, hv.y, acc.y * inv);
    r.z = fmaf(deg, hv.z, acc.z * inv);
    r.w = fmaf(deg, hv.w, acc.w * inv);
    float4 q;
    q.x = __shfl_xor_sync(0xffffffffu, r.x, 16);
    q.y = __shfl_xor_sync(0xffffffffu, r.y, 16);
    q.z = __shfl_xor_sync(0xffffffffu, r.z, 16);
    q.w = __shfl_xor_sync(0xffffffffu, r.w, 16);
    if (lane < 16) {
        int dl = lane << 2;
        float4 o4;
        o4.x = 0.5f * (r.x + q.x) + biases[64 + dl + 0];
        o4.y = 0.5f * (r.y + q.y) + biases[64 + dl + 1];
        o4.z = 0.5f * (r.z + q.z) + biases[64 + dl + 2];
        o4.w = 0.5f * (r.w + q.w) + biases[64 + dl + 3];
        *(float4*)(out + (size_t)n * 64 + dl) = o4;
    }
}

// ======================= launch =======================
extern "C" void kernel_launch(void* const* d_in, const int* in_sizes, int n_in,
                              void* d_out, int out_size) {
    const int* x = (const int*)d_in[0];
    const int* ei = (const int*)d_in[1];
    const float* emb = (const float*)d_in[2];
    const float* Ws = (const float*)d_in[3];
    const float* bs = (const float*)d_in[4];
    const float* atts = (const float*)d_in[5];
    const float* biases = (const float*)d_in[6];
    float* out = (float*)d_out;

    int n = in_sizes[0];
    int E = in_sizes[1] / 2;

    int nb = (n + 255) / 256;
    int eb = (E + 255) / 256;
    int wb = (n + 7) / 8;

    k_init<<<nb, 256>>>(x, n);
    k_hist<<<eb, 256>>>(ei, x, E);
    k_scan<<<1, 1024>>>(n, emb, Ws, bs, atts);
    k_scatter<<<eb, 256>>>(ei, E);
    k_node<<<wb, 256>>>(x, Ws, bs, atts, biases, n);
    k_aggr<<<wb, 256>>>(biases, out, n);
}

// round 5
// speedup vs baseline: 1.0028x; 1.0027x over previous
#include <cuda_runtime.h>
#include <cuda_fp16.h>

#define NMAX 50000
#define EMAX 800000
#define TOTE (NMAX + EMAX)

// ---- scratch (device globals: no allocation allowed) ----
__device__ int g_cnt[NMAX];          // packed: low16 = degree (incl self), high16 = count(type0) incl self
__device__ int g_rowptr[NMAX + 1];
__device__ int g_cur[NMAX];
__device__ int g_adj[TOTE];
__device__ __align__(16) float g_hl0[256];   // layer-0 linear output, 2 rows x 128
__device__ float g_ew[4];                    // exp(beta0[r,h] - max_r beta0[r,h]) : [r*2+h]
__device__ __align__(16) float g_hlinf[(size_t)NMAX * 128];  // layer-1 linear output fp32 (self reads)
__device__ __align__(16) __half g_hlinh[(size_t)NMAX * 128]; // fp16 copy (neighbor gathers)
__device__ __align__(16) float g_beta[(size_t)NMAX * 2];     // layer-1 logits per node/head

__device__ __forceinline__ float leaky(float v) { return v > 0.f ? v : 0.2f * v; }

// exp(x) for x <= 0, FMA-pipe only (no MUFU). Taylor-6 on 2^f, f in [0,1).
__device__ __forceinline__ float fexp(float x) {
    float t = fmaxf(x * 1.4426950408889634f, -126.f);
    float n = floorf(t);
    float f = t - n;
    float p = 1.5403530394e-4f;
    p = fmaf(p, f, 1.3333558146e-3f);
    p = fmaf(p, f, 9.6181291076e-3f);
    p = fmaf(p, f, 5.5504108665e-2f);
    p = fmaf(p, f, 2.4022650696e-1f);
    p = fmaf(p, f, 6.9314718056e-1f);
    p = fmaf(p, f, 1.0f);
    float s = __int_as_float(((int)n + 127) << 23);
    return p * s;
}

// ======================= CSR build =======================
__global__ void k_init(const int* __restrict__ x, int n) {
    int i = blockIdx.x * blockDim.x + threadIdx.x;
    if (i < n) g_cnt[i] = 1 + ((x[i] == 0) << 16);   // self-loop
}

__global__ void k_hist(const int* __restrict__ ei, const int* __restrict__ x, int E) {
    int e = blockIdx.x * blockDim.x + threadIdx.x;
    if (e < E) {
        int d = ei[E + e];
        int p = 1 + ((__ldg(&x[d]) == 0) << 16);
        atomicAdd(&g_cnt[ei[e]], p);
    }
}

// single block: prefix sum of degrees + scatter-init + layer-0 prep (tiny)
__global__ void k_scan(int n, const float* __restrict__ emb, const float* __restrict__ Ws,
                       const float* __restrict__ bs, const float* __restrict__ atts) {
    __shared__ int part[1024];
    __shared__ float sh[256];
    __shared__ float sb4[4];
    int t = threadIdx.x;
    int chunk = (n + 1023) >> 10;
    int beg = t * chunk;
    int end = min(beg + chunk, n);
    int s = 0;
    for (int i = beg; i < end; i++) s += (g_cnt[i] & 0xffff);
    part[t] = s;
    __syncthreads();
    for (int off = 1; off < 1024; off <<= 1) {
        int tmp = (t >= off) ? part[t - off] : 0;
        __syncthreads();
        part[t] += tmp;
        __syncthreads();
    }
    int run = part[t] - s;
    for (int i = beg; i < end; i++) {
        int deg = g_cnt[i] & 0xffff;
        g_rowptr[i] = run;
        g_adj[run] = i;       // self-loop first
        g_cur[i] = run + 1;
        run += deg;
    }
    if (t == 0) g_rowptr[n] = part[1023];
    __syncthreads();
    // layer-0 linear (2 rows x 128)
    if (t < 256) {
        int row = t >> 7, col = t & 127;
        float acc = bs[col];
#pragma unroll
        for (int k = 0; k < 64; k++) acc += emb[row * 64 + k] * Ws[k * 128 + col];
        g_hl0[t] = acc;
        sh[t] = acc;
    }
    __syncthreads();
    if (t < 4) {
        int r = t >> 1, h = t & 1;
        float sum = 0.f;
        for (int d = 0; d < 64; d++) sum += sh[r * 128 + h * 64 + d] * atts[h * 64 + d];
        sb4[r * 2 + h] = leaky(sum);
    }
    __syncthreads();
    if (t < 4) {
        int h = t & 1;
        float m = fmaxf(sb4[h], sb4[2 + h]);
        g_ew[t] = fexp(sb4[t] - m);
    }
}

__global__ void k_scatter(const int* __restrict__ ei, int E) {
    int e = blockIdx.x * blockDim.x + threadIdx.x;
    if (e < E) {
        int s = ei[e];
        int d = ei[E + e];
        int p = atomicAdd(&g_cur[s], 1);
        g_adj[p] = d;
    }
}

// ======================= fused node kernel =======================
// Layer-0 aggregation (closed form from type counts) -> layer-1 linear (warp-per-node)
// -> layer-1 attention logits. No adjacency reads, no exp.
__global__ __launch_bounds__(256) void k_node(const int* __restrict__ x,
                                              const float* __restrict__ Ws,
                                              const float* __restrict__ bs,
                                              const float* __restrict__ atts,
                                              const float* __restrict__ biases, int n_nodes) {
    __shared__ float4 sW[64 * 32];  // sW[k*32+l] = {W1[k][l], W1[k][l+32], W1[k][l+64], W1[k][l+96]}
    __shared__ float sx[8][64];
    __shared__ float sh0[256];
    __shared__ float sew[4];
    const float* W1 = Ws + 64 * 128;
    const float* b1 = bs + 128;
    const float* att1 = atts + 128;
    for (int idx = threadIdx.x; idx < 2048; idx += 256) {
        int k = idx >> 5, l = idx & 31;
        const float* wr = W1 + k * 128 + l;
        sW[idx] = make_float4(wr[0], wr[32], wr[64], wr[96]);
    }
    for (int idx = threadIdx.x; idx < 256; idx += 256) sh0[idx] = g_hl0[idx];
    if (threadIdx.x < 4) sew[threadIdx.x] = g_ew[threadIdx.x];
    __syncthreads();

    int warp = threadIdx.x >> 5, lane = threadIdx.x & 31;
    int n = blockIdx.x * 8 + warp;
    if (n >= n_nodes) return;

    int packed = g_cnt[n];
    float deg = (float)(packed & 0xffff);
    float c0f = (float)(packed >> 16);
    float c1f = deg - c0f;
    // per-head softmax-weighted neighbor mix coefficients
    float w00 = sew[0], w01 = sew[1], w10 = sew[2], w11 = sew[3];
    float den0 = c0f * w00 + c1f * w10 + 1e-16f;
    float den1 = c0f * w01 + c1f * w11 + 1e-16f;
    float A0 = c0f * w00 / den0, B0 = c1f * w10 / den0;
    float A1 = c0f * w01 / den1, B1 = c1f * w11 / den1;
    int tp = x[n];
    const float* vt = sh0 + (tp ? 128 : 0);

    // layer-0 output for d = lane, lane+32 (mean over heads + bias, relu)
#pragma unroll
    for (int r = 0; r < 2; r++) {
        int d = lane + r * 32;
        float f0 = deg * vt[d] + A0 * sh0[d] + B0 * sh0[128 + d];           // head 0 (col d)
        float f1 = deg * vt[64 + d] + A1 * sh0[64 + d] + B1 * sh0[192 + d]; // head 1 (col 64+d)
        sx[warp][d] = fmaxf(0.f, fmaf(0.5f, f0 + f1, biases[d]));
    }
    __syncwarp();

    // layer-1 linear: [64] @ W1[64,128] + b1
    float4 acc = make_float4(b1[lane], b1[lane + 32], b1[lane + 64], b1[lane + 96]);
#pragma unroll
    for (int k = 0; k < 64; k++) {
        float xk = sx[warp][k];
        float4 w = sW[(k << 5) + lane];
        acc.x = fmaf(xk, w.x, acc.x);
        acc.y = fmaf(xk, w.y, acc.y);
        acc.z = fmaf(xk, w.z, acc.z);
        acc.w = fmaf(xk, w.w, acc.w);
    }
    float* o = g_hlinf + (size_t)n * 128;
    o[lane] = acc.x;
    o[lane + 32] = acc.y;
    o[lane + 64] = acc.z;
    o[lane + 96] = acc.w;
    __half* oh = g_hlinh + (size_t)n * 128;
    oh[lane] = __float2half_rn(acc.x);
    oh[lane + 32] = __float2half_rn(acc.y);
    oh[lane + 64] = __float2half_rn(acc.z);
    oh[lane + 96] = __float2half_rn(acc.w);
    // attention logits: head0 = cols [0,64), head1 = cols [64,128)
    float p0 = acc.x * att1[lane] + acc.y * att1[lane + 32];
    float p1 = acc.z * att1[64 + lane] + acc.w * att1[96 + lane];
#pragma unroll
    for (int off = 16; off; off >>= 1) {
        p0 += __shfl_xor_sync(0xffffffffu, p0, off);
        p1 += __shfl_xor_sync(0xffffffffu, p1, off);
    }
    if (lane == 0) {
        g_beta[2 * n] = leaky(p0);
        g_beta[2 * n + 1] = leaky(p1);
    }
}

// ======================= layer-1 aggregation =======================
// Warp per node. Pass 1: segment max (no exp). Pass 2: chunks of 32 edges —
// each lane computes the softmax weight for ITS edge once (FMA-pipe exp), parks
// it in smem; the vector-gather loop broadcasts weights via LDS. fp16 gathers.
__global__ __launch_bounds__(256) void k_aggr(const float* __restrict__ biases,
                                              float* __restrict__ out, int n_nodes) {
    __shared__ int sd[8][32];
    __shared__ float2 swt[8][32];
    int warp = threadIdx.x >> 5, lane = threadIdx.x & 31;
    int n = blockIdx.x * 8 + warp;
    if (n >= n_nodes) return;
    int s = g_rowptr[n], e = g_rowptr[n + 1];

    // pass 1: per-head max over neighbors
    float m0 = -3e38f, m1 = -3e38f;
    for (int i = s + lane; i < e; i += 32) {
        int d = g_adj[i];
        float2 b = *(const float2*)(g_beta + 2 * d);
        m0 = fmaxf(m0, b.x);
        m1 = fmaxf(m1, b.y);
    }
#pragma unroll
    for (int o = 16; o; o >>= 1) {
        m0 = fmaxf(m0, __shfl_xor_sync(0xffffffffu, m0, o));
        m1 = fmaxf(m1, __shfl_xor_sync(0xffffffffu, m1, o));
    }

    int head = lane >> 4;  // lane covers columns [4*lane, 4*lane+4)
    float4 acc = make_float4(0.f, 0.f, 0.f, 0.f);
    float den0 = 0.f, den1 = 0.f;

    for (int base = s; base < e; base += 32) {
        int i = base + lane;
        bool valid = i < e;
        int d = valid ? g_adj[i] : 0;
        float w0 = 0.f, w1 = 0.f;
        if (valid) {
            float2 b = *(const float2*)(g_beta + 2 * d);
            w0 = fexp(b.x - m0);
            w1 = fexp(b.y - m1);
        }
        sd[warp][lane] = d;
        swt[warp][lane] = make_float2(w0, w1);
        den0 += w0;
        den1 += w1;
        __syncwarp();
        int cnt = min(32, e - base);
#pragma unroll 4
        for (int j = 0; j < cnt; j++) {
            int dd = sd[warp][j];
            float2 wp = swt[warp][j];
            float w = head ? wp.y : wp.x;
            const uint2* rowh = (const uint2*)(g_hlinh + (size_t)dd * 128);
            uint2 pk = __ldg(&rowh[lane]);
            __half2 h01 = *(__half2*)&pk.x;
            __half2 h23 = *(__half2*)&pk.y;
            float2 f01 = __half22float2(h01);
            float2 f23 = __half22float2(h23);
            acc.x = fmaf(w, f01.x, acc.x);
            acc.y = fmaf(w, f01.y, acc.y);
            acc.z = fmaf(w, f23.x, acc.z);
            acc.w = fmaf(w, f23.y, acc.w);
        }
        __syncwarp();
    }
#pragma unroll
    for (int o = 16; o; o >>= 1) {
        den0 += __shfl_xor_sync(0xffffffffu, den0, o);
        den1 += __shfl_xor_sync(0xffffffffu, den1, o);
    }
    float inv = 1.f / ((head ? den1 : den0) + 1e-16f);
    float deg = (float)(e - s);
    float4 hv = *(const float4*)(g_hlinf + (size_t)n * 128 + (lane << 2));
    float4 r;
    r.x = fmaf(deg, hv.x, acc.x * inv);
    r.y = fmaf(deg, hv.y, acc.y * inv);
    r.z = fmaf(deg, hv.z, acc.z * inv);
    r.w = fmaf(deg, hv.w, acc.w * inv);
    float4 q;
    q.x = __shfl_xor_sync(0xffffffffu, r.x, 16);
    q.y = __shfl_xor_sync(0xffffffffu, r.y, 16);
    q.z = __shfl_xor_sync(0xffffffffu, r.z, 16);
    q.w = __shfl_xor_sync(0xffffffffu, r.w, 16);
    if (lane < 16) {
        int dl = lane << 2;
        float4 o4;
        o4.x = 0.5f * (r.x + q.x) + biases[64 + dl + 0];
        o4.y = 0.5f * (r.y + q.y) + biases[64 + dl + 1];
        o4.z = 0.5f * (r.z + q.z) + biases[64 + dl + 2];
        o4.w = 0.5f * (r.w + q.w) + biases[64 + dl + 3];
        *(float4*)(out + (size_t)n * 64 + dl) = o4;
    }
}

// ======================= launch =======================
extern "C" void kernel_launch(void* const* d_in, const int* in_sizes, int n_in,
                              void* d_out, int out_size) {
    const int* x = (const int*)d_in[0];
    const int* ei = (const int*)d_in[1];
    const float* emb = (const float*)d_in[2];
    const float* Ws = (const float*)d_in[3];
    const float* bs = (const float*)d_in[4];
    const float* atts = (const float*)d_in[5];
    const float* biases = (const float*)d_in[6];
    float* out = (float*)d_out;

    int n = in_sizes[0];
    int E = in_sizes[1] / 2;

    int nb = (n + 255) / 256;
    int eb = (E + 255) / 256;
    int wb = (n + 7) / 8;

    k_init<<<nb, 256>>>(x, n);
    k_hist<<<eb, 256>>>(ei, x, E);
    k_scan<<<1, 1024>>>(n, emb, Ws, bs, atts);
    k_scatter<<<eb, 256>>>(ei, E);
    k_node<<<wb, 256>>>(x, Ws, bs, atts, biases, n);
    k_aggr<<<wb, 256>>>(biases, out, n);
}